// round 2
// baseline (speedup 1.0000x reference)
#include <cuda_runtime.h>

// ---------------------------------------------------------------------------
// GATv2 layer, fused:  B=8,T=32,N=64,F=64,U=64,H=4  (BT=256 graphs)
// grid = (256 bt, 4 heads), 256 threads/CTA, everything in SMEM.
// fp32 throughout; packed f32x2 math in the pairwise hot loop.
// ---------------------------------------------------------------------------

static constexpr int BT = 256;
static constexpr int LD = 68;   // padded row stride (floats) for 64x64 tiles

// per-head partial outputs: 4 x (256*64*64) floats = 16 MB scratch
__device__ float g_part[4 * BT * 64 * 64];

// ---- packed f32x2 helpers (sm_100a) ---------------------------------------
__device__ __forceinline__ unsigned long long pack2(float lo, float hi) {
    unsigned long long r;
    asm("mov.b64 %0, {%1,%2};" : "=l"(r) : "f"(lo), "f"(hi));
    return r;
}
__device__ __forceinline__ void unpack2(unsigned long long v, float& lo, float& hi) {
    asm("mov.b64 {%0,%1}, %2;" : "=f"(lo), "=f"(hi) : "l"(v));
}
__device__ __forceinline__ unsigned long long add2(unsigned long long a, unsigned long long b) {
    unsigned long long r;
    asm("add.rn.f32x2 %0, %1, %2;" : "=l"(r) : "l"(a), "l"(b));
    return r;
}
__device__ __forceinline__ unsigned long long fma2(unsigned long long a, unsigned long long b,
                                                   unsigned long long c) {
    unsigned long long r;
    asm("fma.rn.f32x2 %0, %1, %2, %3;" : "=l"(r) : "l"(a), "l"(b), "l"(c));
    return r;
}
// relu on both halves: pack/unpack alias to the register pair; FMNMX on alu pipe
__device__ __forceinline__ unsigned long long relu2(unsigned long long v) {
    float lo, hi;
    unpack2(v, lo, hi);
    lo = fmaxf(lo, 0.0f);
    hi = fmaxf(hi, 0.0f);
    return pack2(lo, hi);
}
__device__ __forceinline__ float f4get(const float4& v, int i) {
    switch (i & 3) { case 0: return v.x; case 1: return v.y; case 2: return v.z; default: return v.w; }
}

__global__ void __launch_bounds__(256, 2) gat_head_kernel(
    const float* __restrict__ feat,   // [256,64,64]
    const int*   __restrict__ adj,    // [8,64,64]
    const float* __restrict__ Wsrc,   // [4,64,64]
    const float* __restrict__ Wdst,   // [4,64,64]
    const float* __restrict__ avec)   // [4,64]
{
    extern __shared__ float sm[];
    float* R0 = sm;             // X           -> scores/attn
    float* R1 = sm + 64 * LD;   // Wsrc        -> Dt (D transposed [u][j])
    float* R2 = sm + 128 * LD;  // Wdst        -> S  (row-major [i][u])
    float* aS = sm + 192 * LD;  // a[64]
    float* a8 = aS + 64;        // 0.8*a
    float* ps = a8 + 64;        // p_i = S.a
    float* qs = ps + 64;        // q_j = D.a
    unsigned long long* adjb = (unsigned long long*)(qs + 64);  // mask bits per row

    const int tid = threadIdx.x;
    const int bt  = blockIdx.x;
    const int h   = blockIdx.y;
    const int b   = bt >> 5;    // T = 32

    // ---- stage inputs into smem (coalesced float4) ----
    {
        const float4* fp  = (const float4*)(feat + bt * 4096);
        const float4* wsp = (const float4*)(Wsrc + h * 4096);
        const float4* wdp = (const float4*)(Wdst + h * 4096);
        for (int k = tid; k < 1024; k += 256) {
            int r = k >> 4, c = (k & 15) << 2;
            *(float4*)&R0[r * LD + c] = fp[k];
            *(float4*)&R1[r * LD + c] = wsp[k];
            *(float4*)&R2[r * LD + c] = wdp[k];
        }
    }
    if (tid < 64) {
        float av = avec[h * 64 + tid];
        aS[tid] = av;
        a8[tid] = 0.8f * av;
        const int* ar = adj + b * 4096 + tid * 64;
        unsigned long long m = 1ull << tid;   // self loop always on
        #pragma unroll 8
        for (int j = 0; j < 64; j++)
            if (ar[j] > 0) m |= (1ull << j);
        adjb[tid] = m;
    }
    __syncthreads();

    // ---- projections: S = X @ Wsrc, D = X @ Wdst  (16x16 threads, 4x4 tiles) ----
    const int ty = tid >> 4, tx = tid & 15;
    const int r0 = ty << 2, c0 = tx << 2;
    float accS[4][4], accD[4][4];
    #pragma unroll
    for (int i = 0; i < 4; i++)
        #pragma unroll
        for (int j = 0; j < 4; j++) { accS[i][j] = 0.f; accD[i][j] = 0.f; }

    #pragma unroll 2
    for (int f0 = 0; f0 < 64; f0 += 4) {
        float4 xv0 = *(const float4*)&R0[(r0 + 0) * LD + f0];
        float4 xv1 = *(const float4*)&R0[(r0 + 1) * LD + f0];
        float4 xv2 = *(const float4*)&R0[(r0 + 2) * LD + f0];
        float4 xv3 = *(const float4*)&R0[(r0 + 3) * LD + f0];
        #pragma unroll
        for (int ff = 0; ff < 4; ff++) {
            float4 ws = *(const float4*)&R1[(f0 + ff) * LD + c0];
            float4 wd = *(const float4*)&R2[(f0 + ff) * LD + c0];
            float x0 = f4get(xv0, ff), x1 = f4get(xv1, ff);
            float x2 = f4get(xv2, ff), x3 = f4get(xv3, ff);
#define PROJ_ROW(K, XK)                                                          \
            accS[K][0] += XK * ws.x; accS[K][1] += XK * ws.y;                    \
            accS[K][2] += XK * ws.z; accS[K][3] += XK * ws.w;                    \
            accD[K][0] += XK * wd.x; accD[K][1] += XK * wd.y;                    \
            accD[K][2] += XK * wd.z; accD[K][3] += XK * wd.w;
            PROJ_ROW(0, x0) PROJ_ROW(1, x1) PROJ_ROW(2, x2) PROJ_ROW(3, x3)
#undef PROJ_ROW
        }
    }
    __syncthreads();   // all reads of X/Wsrc/Wdst complete

    // S row-major into R2
    #pragma unroll
    for (int k = 0; k < 4; k++) {
        float4 v = make_float4(accS[k][0], accS[k][1], accS[k][2], accS[k][3]);
        *(float4*)&R2[(r0 + k) * LD + c0] = v;
    }
    // D transposed into R1 (lane-rotated scatter to cut bank conflicts)
    #pragma unroll
    for (int k = 0; k < 4; k++) {
        #pragma unroll
        for (int idx = 0; idx < 4; idx++) {
            int cc = (idx + tx) & 3;
            R1[(c0 + cc) * LD + (r0 + k)] = accD[k][cc];
        }
    }
    __syncthreads();

    // ---- p_i = S[i,:].a,  q_j = D[j,:].a ----
    if (tid < 64) {
        float accp = 0.f, accq = 0.f;
        #pragma unroll 8
        for (int u = 0; u < 64; u++) {
            accp += aS[u] * R2[tid * LD + u];
            accq += aS[u] * R1[u * LD + tid];
        }
        ps[tid] = accp;
        qs[tid] = accq;
    }
    __syncthreads();

    // ---- pairwise scores: 0.2*(p_i+q_j) + sum_u 0.8*a_u * relu(s_iu + d_ju) ----
    {
        unsigned long long acc0[4], acc1[4];   // acc0: cols j0,j0+1  acc1: j0+2,j0+3
        #pragma unroll
        for (int ii = 0; ii < 4; ii++) { acc0[ii] = 0ull; acc1[ii] = 0ull; }

        #pragma unroll 2
        for (int u4 = 0; u4 < 64; u4 += 4) {
            float4 a84 = *(const float4*)&a8[u4];
            float4 srow0 = *(const float4*)&R2[(r0 + 0) * LD + u4];
            float4 srow1 = *(const float4*)&R2[(r0 + 1) * LD + u4];
            float4 srow2 = *(const float4*)&R2[(r0 + 2) * LD + u4];
            float4 srow3 = *(const float4*)&R2[(r0 + 3) * LD + u4];
            #pragma unroll
            for (int uu = 0; uu < 4; uu++) {
                ulonglong2 d2 = *(const ulonglong2*)&R1[(u4 + uu) * LD + c0];
                float a8u = f4get(a84, uu);
                unsigned long long a2 = pack2(a8u, a8u);
#define PAIR_ROW(K, SR)                                                          \
                {                                                                \
                    float s_ = f4get(SR, uu);                                    \
                    unsigned long long s2_ = pack2(s_, s_);                      \
                    acc0[K] = fma2(a2, relu2(add2(s2_, d2.x)), acc0[K]);         \
                    acc1[K] = fma2(a2, relu2(add2(s2_, d2.y)), acc1[K]);         \
                }
                PAIR_ROW(0, srow0) PAIR_ROW(1, srow1) PAIR_ROW(2, srow2) PAIR_ROW(3, srow3)
#undef PAIR_ROW
            }
        }
        float q0 = qs[c0 + 0], q1 = qs[c0 + 1], q2 = qs[c0 + 2], q3 = qs[c0 + 3];
        #pragma unroll
        for (int ii = 0; ii < 4; ii++) {
            float pi = ps[r0 + ii];
            float v0, v1, v2, v3;
            unpack2(acc0[ii], v0, v1);
            unpack2(acc1[ii], v2, v3);
            float4 sc;
            sc.x = 0.2f * (pi + q0) + v0;
            sc.y = 0.2f * (pi + q1) + v1;
            sc.z = 0.2f * (pi + q2) + v2;
            sc.w = 0.2f * (pi + q3) + v3;
            *(float4*)&R0[(r0 + ii) * LD + c0] = sc;   // scores into R0
        }
    }
    __syncthreads();

    // ---- masked softmax over j (4 threads per row, shfl within quad) ----
    {
        int row = tid >> 2, qd = tid & 3;
        float* srow = R0 + row * LD + (qd << 4);
        unsigned mb = (unsigned)(adjb[row] >> (qd << 4)) & 0xFFFFu;
        float vals[16];
        float mx = -3.0e38f;
        #pragma unroll
        for (int c = 0; c < 16; c++) {
            float v = ((mb >> c) & 1u) ? srow[c] : -1e9f;
            vals[c] = v;
            mx = fmaxf(mx, v);
        }
        mx = fmaxf(mx, __shfl_xor_sync(0xffffffffu, mx, 1));
        mx = fmaxf(mx, __shfl_xor_sync(0xffffffffu, mx, 2));
        float ssum = 0.f;
        #pragma unroll
        for (int c = 0; c < 16; c++) {
            float e = exp2f((vals[c] - mx) * 1.4426950408889634f);  // masked -> 0
            vals[c] = e;
            ssum += e;
        }
        ssum += __shfl_xor_sync(0xffffffffu, ssum, 1);
        ssum += __shfl_xor_sync(0xffffffffu, ssum, 2);
        float inv = 1.0f / ssum;
        #pragma unroll
        for (int c = 0; c < 16; c++)
            srow[c] = vals[c] * inv;
    }
    __syncthreads();

    // ---- aggregation: out[i,u] = sum_j attn[i,j] * S[j,u] ----
    {
        const int w = tid >> 5, l = tid & 31;   // warp w -> rows 8w..8w+7, lane -> u pair
        float acc[8][2];
        #pragma unroll
        for (int ii = 0; ii < 8; ii++) { acc[ii][0] = 0.f; acc[ii][1] = 0.f; }

        #pragma unroll 2
        for (int j4 = 0; j4 < 64; j4 += 4) {
            float2 sv0 = *(const float2*)&R2[(j4 + 0) * LD + (l << 1)];
            float2 sv1 = *(const float2*)&R2[(j4 + 1) * LD + (l << 1)];
            float2 sv2 = *(const float2*)&R2[(j4 + 2) * LD + (l << 1)];
            float2 sv3 = *(const float2*)&R2[(j4 + 3) * LD + (l << 1)];
            #pragma unroll
            for (int ii = 0; ii < 8; ii++) {
                float4 av = *(const float4*)&R0[(w * 8 + ii) * LD + j4];
                acc[ii][0] = fmaf(av.x, sv0.x, fmaf(av.y, sv1.x,
                             fmaf(av.z, sv2.x, fmaf(av.w, sv3.x, acc[ii][0]))));
                acc[ii][1] = fmaf(av.x, sv0.y, fmaf(av.y, sv1.y,
                             fmaf(av.z, sv2.y, fmaf(av.w, sv3.y, acc[ii][1]))));
            }
        }
        float* op = g_part + h * (BT * 4096) + bt * 4096;
        #pragma unroll
        for (int ii = 0; ii < 8; ii++)
            *(float2*)&op[(w * 8 + ii) * 64 + (l << 1)] = make_float2(acc[ii][0], acc[ii][1]);
    }
}

// ---- average the 4 head partials into d_out --------------------------------
__global__ void combine_kernel(float4* __restrict__ out) {
    int i = blockIdx.x * blockDim.x + threadIdx.x;   // 262144 float4s
    const float4* p = (const float4*)g_part;
    float4 a = p[i];
    float4 b = p[i + 262144];
    float4 c = p[i + 524288];
    float4 d = p[i + 786432];
    out[i] = make_float4(0.25f * (a.x + b.x + c.x + d.x),
                         0.25f * (a.y + b.y + c.y + d.y),
                         0.25f * (a.z + b.z + c.z + d.z),
                         0.25f * (a.w + b.w + c.w + d.w));
}

extern "C" void kernel_launch(void* const* d_in, const int* in_sizes, int n_in,
                              void* d_out, int out_size) {
    const float* feat = (const float*)d_in[0];
    const int*   adj  = (const int*)d_in[1];
    const float* Wsrc = (const float*)d_in[2];
    const float* Wdst = (const float*)d_in[3];
    const float* avec = (const float*)d_in[4];

    const int smem = (192 * LD + 256) * (int)sizeof(float) + 64 * (int)sizeof(unsigned long long);
    cudaFuncSetAttribute((const void*)gat_head_kernel,
                         cudaFuncAttributeMaxDynamicSharedMemorySize, smem);

    gat_head_kernel<<<dim3(BT, 4), 256, smem>>>(feat, adj, Wsrc, Wdst, avec);
    combine_kernel<<<1024, 256>>>((float4*)d_out);
}

// round 3
// speedup vs baseline: 1.0585x; 1.0585x over previous
#include <cuda_runtime.h>

// ---------------------------------------------------------------------------
// GATv2 fused, all 4 heads per CTA:  B=8,T=32,N=64,F=64,U=64,H=4  (BT=256)
// grid = 256 CTAs (one per graph), 256 threads, occ 2 -> exactly one wave.
// fp32 throughout; packed f32x2 math in projection, pairwise, aggregation.
// Head outputs accumulated in registers; final mean written directly.
// ---------------------------------------------------------------------------

static constexpr int LD = 68;   // padded row stride (floats) for 64x64 tiles

// ---- packed f32x2 helpers (sm_100a) ---------------------------------------
__device__ __forceinline__ unsigned long long pack2(float lo, float hi) {
    unsigned long long r;
    asm("mov.b64 %0, {%1,%2};" : "=l"(r) : "f"(lo), "f"(hi));
    return r;
}
__device__ __forceinline__ void unpack2(unsigned long long v, float& lo, float& hi) {
    asm("mov.b64 {%0,%1}, %2;" : "=f"(lo), "=f"(hi) : "l"(v));
}
__device__ __forceinline__ unsigned long long add2(unsigned long long a, unsigned long long b) {
    unsigned long long r;
    asm("add.rn.f32x2 %0, %1, %2;" : "=l"(r) : "l"(a), "l"(b));
    return r;
}
__device__ __forceinline__ unsigned long long fma2(unsigned long long a, unsigned long long b,
                                                   unsigned long long c) {
    unsigned long long r;
    asm("fma.rn.f32x2 %0, %1, %2, %3;" : "=l"(r) : "l"(a), "l"(b), "l"(c));
    return r;
}
// relu on both halves (FMNMX on alu pipe; pack/unpack alias the register pair)
__device__ __forceinline__ unsigned long long relu2(unsigned long long v) {
    float lo, hi;
    unpack2(v, lo, hi);
    lo = fmaxf(lo, 0.0f);
    hi = fmaxf(hi, 0.0f);
    return pack2(lo, hi);
}
__device__ __forceinline__ float f4get(const float4& v, int i) {
    switch (i & 3) { case 0: return v.x; case 1: return v.y; case 2: return v.z; default: return v.w; }
}

__global__ void __launch_bounds__(256, 2) gat_fused_kernel(
    const float* __restrict__ feat,   // [256,64,64]
    const int*   __restrict__ adj,    // [8,64,64]
    const float* __restrict__ Wsrc,   // [4,64,64]
    const float* __restrict__ Wdst,   // [4,64,64]
    const float* __restrict__ avec,   // [4,64]
    float*       __restrict__ outp)   // [256,64,64]
{
    extern __shared__ float sm[];
    float* XS = sm;             // X (persists across heads)
    float* B1 = sm + 64 * LD;   // Wsrc -> Dt (D transposed [u][j])
    float* B2 = sm + 128 * LD;  // Wdst -> S  (row-major [i][u])
    float* B3 = sm + 192 * LD;  // scores / attn
    float* aS = sm + 256 * LD;  // a[64]
    float* a8 = aS + 64;        // 0.8*a
    float* ps = a8 + 64;        // p_i = S.a
    float* qs = ps + 64;        // q_j = D.a
    unsigned long long* adjb = (unsigned long long*)(qs + 64);  // mask bits per row

    const int tid = threadIdx.x;
    const int bt  = blockIdx.x;
    const int b   = bt >> 5;    // T = 32

    const int ty = tid >> 4, tx = tid & 15;
    const int r0 = ty << 2, c0 = tx << 2;
    const int w = tid >> 5, l = tid & 31;

    // ---- stage X + adjacency mask once ----
    {
        const float4* fp = (const float4*)(feat + bt * 4096);
        for (int k = tid; k < 1024; k += 256) {
            int r = k >> 4, c = (k & 15) << 2;
            *(float4*)&XS[r * LD + c] = fp[k];
        }
    }
    if (tid < 64) {
        const int* ar = adj + b * 4096 + tid * 64;
        unsigned long long m = 1ull << tid;   // self loop always on
        #pragma unroll 8
        for (int j = 0; j < 64; j++)
            if (ar[j] > 0) m |= (1ull << j);
        adjb[tid] = m;
    }

    // persistent output accumulator: rows w*8..w*8+7, u-pair (l*2, l*2+1)
    unsigned long long accO[8];
    #pragma unroll
    for (int ii = 0; ii < 8; ii++) accO[ii] = 0ull;

    for (int h = 0; h < 4; h++) {
        // ---- stage this head's weights ----
        {
            const float4* wsp = (const float4*)(Wsrc + h * 4096);
            const float4* wdp = (const float4*)(Wdst + h * 4096);
            for (int k = tid; k < 1024; k += 256) {
                int r = k >> 4, c = (k & 15) << 2;
                *(float4*)&B1[r * LD + c] = wsp[k];
                *(float4*)&B2[r * LD + c] = wdp[k];
            }
            if (tid < 64) {
                float av = avec[h * 64 + tid];
                aS[tid] = av;
                a8[tid] = 0.8f * av;
            }
        }
        __syncthreads();

        // ---- projections: S = X@Wsrc, D = X@Wdst  (packed f32x2, col pairs) ----
        unsigned long long accS[4][2], accD[4][2];
        #pragma unroll
        for (int i = 0; i < 4; i++) {
            accS[i][0] = accS[i][1] = 0ull;
            accD[i][0] = accD[i][1] = 0ull;
        }

        #pragma unroll 2
        for (int f0 = 0; f0 < 64; f0 += 4) {
            float4 xv0 = *(const float4*)&XS[(r0 + 0) * LD + f0];
            float4 xv1 = *(const float4*)&XS[(r0 + 1) * LD + f0];
            float4 xv2 = *(const float4*)&XS[(r0 + 2) * LD + f0];
            float4 xv3 = *(const float4*)&XS[(r0 + 3) * LD + f0];
            #pragma unroll
            for (int ff = 0; ff < 4; ff++) {
                ulonglong2 ws = *(const ulonglong2*)&B1[(f0 + ff) * LD + c0];
                ulonglong2 wd = *(const ulonglong2*)&B2[(f0 + ff) * LD + c0];
                unsigned long long x0 = pack2(f4get(xv0, ff), f4get(xv0, ff));
                unsigned long long x1 = pack2(f4get(xv1, ff), f4get(xv1, ff));
                unsigned long long x2 = pack2(f4get(xv2, ff), f4get(xv2, ff));
                unsigned long long x3 = pack2(f4get(xv3, ff), f4get(xv3, ff));
#define PROJ_ROW(K, XK)                                                      \
                accS[K][0] = fma2(XK, ws.x, accS[K][0]);                     \
                accS[K][1] = fma2(XK, ws.y, accS[K][1]);                     \
                accD[K][0] = fma2(XK, wd.x, accD[K][0]);                     \
                accD[K][1] = fma2(XK, wd.y, accD[K][1]);
                PROJ_ROW(0, x0) PROJ_ROW(1, x1) PROJ_ROW(2, x2) PROJ_ROW(3, x3)
#undef PROJ_ROW
            }
        }
        __syncthreads();   // all reads of Wsrc/Wdst complete

        // S row-major into B2 (packed pair stores)
        #pragma unroll
        for (int k = 0; k < 4; k++) {
            ulonglong2 v;
            v.x = accS[k][0];
            v.y = accS[k][1];
            *(ulonglong2*)&B2[(r0 + k) * LD + c0] = v;
        }
        // D transposed into B1 (lane-rotated scatter to cut bank conflicts)
        #pragma unroll
        for (int k = 0; k < 4; k++) {
            float dv[4];
            unpack2(accD[k][0], dv[0], dv[1]);
            unpack2(accD[k][1], dv[2], dv[3]);
            #pragma unroll
            for (int idx = 0; idx < 4; idx++) {
                int cc = (idx + tx) & 3;
                B1[(c0 + cc) * LD + (r0 + k)] = dv[cc];
            }
        }
        __syncthreads();

        // ---- p_i = S[i,:].a,  q_j = D[j,:].a ----
        if (tid < 64) {
            float accp = 0.f, accq = 0.f;
            #pragma unroll 8
            for (int u = 0; u < 64; u++) {
                accp += aS[u] * B2[tid * LD + u];
                accq += aS[u] * B1[u * LD + tid];
            }
            ps[tid] = accp;
            qs[tid] = accq;
        }
        __syncthreads();

        // ---- pairwise: 0.2*(p_i+q_j) + sum_u 0.8*a_u * relu(s_iu + d_ju) ----
        {
            unsigned long long acc0[4], acc1[4];
            #pragma unroll
            for (int ii = 0; ii < 4; ii++) { acc0[ii] = 0ull; acc1[ii] = 0ull; }

            #pragma unroll 2
            for (int u4 = 0; u4 < 64; u4 += 4) {
                float4 a84 = *(const float4*)&a8[u4];
                float4 srow0 = *(const float4*)&B2[(r0 + 0) * LD + u4];
                float4 srow1 = *(const float4*)&B2[(r0 + 1) * LD + u4];
                float4 srow2 = *(const float4*)&B2[(r0 + 2) * LD + u4];
                float4 srow3 = *(const float4*)&B2[(r0 + 3) * LD + u4];
                #pragma unroll
                for (int uu = 0; uu < 4; uu++) {
                    ulonglong2 d2 = *(const ulonglong2*)&B1[(u4 + uu) * LD + c0];
                    float a8u = f4get(a84, uu);
                    unsigned long long a2 = pack2(a8u, a8u);
#define PAIR_ROW(K, SR)                                                      \
                    {                                                        \
                        float s_ = f4get(SR, uu);                            \
                        unsigned long long s2_ = pack2(s_, s_);              \
                        acc0[K] = fma2(a2, relu2(add2(s2_, d2.x)), acc0[K]); \
                        acc1[K] = fma2(a2, relu2(add2(s2_, d2.y)), acc1[K]); \
                    }
                    PAIR_ROW(0, srow0) PAIR_ROW(1, srow1) PAIR_ROW(2, srow2) PAIR_ROW(3, srow3)
#undef PAIR_ROW
                }
            }
            float q0 = qs[c0 + 0], q1 = qs[c0 + 1], q2 = qs[c0 + 2], q3 = qs[c0 + 3];
            #pragma unroll
            for (int ii = 0; ii < 4; ii++) {
                float pi = ps[r0 + ii];
                float v0, v1, v2, v3;
                unpack2(acc0[ii], v0, v1);
                unpack2(acc1[ii], v2, v3);
                float4 sc;
                sc.x = 0.2f * (pi + q0) + v0;
                sc.y = 0.2f * (pi + q1) + v1;
                sc.z = 0.2f * (pi + q2) + v2;
                sc.w = 0.2f * (pi + q3) + v3;
                *(float4*)&B3[(r0 + ii) * LD + c0] = sc;
            }
        }
        __syncthreads();

        // ---- masked softmax over j (4 threads per row, shfl within quad) ----
        {
            int row = tid >> 2, qd = tid & 3;
            float* srow = B3 + row * LD + (qd << 4);
            unsigned mb = (unsigned)(adjb[row] >> (qd << 4)) & 0xFFFFu;
            float vals[16];
            float mx = -3.0e38f;
            #pragma unroll
            for (int c = 0; c < 16; c++) {
                float v = ((mb >> c) & 1u) ? srow[c] : -1e9f;
                vals[c] = v;
                mx = fmaxf(mx, v);
            }
            mx = fmaxf(mx, __shfl_xor_sync(0xffffffffu, mx, 1));
            mx = fmaxf(mx, __shfl_xor_sync(0xffffffffu, mx, 2));
            float ssum = 0.f;
            #pragma unroll
            for (int c = 0; c < 16; c++) {
                float e = exp2f((vals[c] - mx) * 1.4426950408889634f);  // masked -> 0
                vals[c] = e;
                ssum += e;
            }
            ssum += __shfl_xor_sync(0xffffffffu, ssum, 1);
            ssum += __shfl_xor_sync(0xffffffffu, ssum, 2);
            float inv = 1.0f / ssum;
            #pragma unroll
            for (int c = 0; c < 16; c++)
                srow[c] = vals[c] * inv;
        }
        __syncthreads();

        // ---- aggregation: accO[i-pairs] += attn @ S  (packed f32x2) ----
        {
            #pragma unroll 2
            for (int j4 = 0; j4 < 64; j4 += 4) {
                unsigned long long sv0 = *(const unsigned long long*)&B2[(j4 + 0) * LD + (l << 1)];
                unsigned long long sv1 = *(const unsigned long long*)&B2[(j4 + 1) * LD + (l << 1)];
                unsigned long long sv2 = *(const unsigned long long*)&B2[(j4 + 2) * LD + (l << 1)];
                unsigned long long sv3 = *(const unsigned long long*)&B2[(j4 + 3) * LD + (l << 1)];
                #pragma unroll
                for (int ii = 0; ii < 8; ii++) {
                    float4 av = *(const float4*)&B3[(w * 8 + ii) * LD + j4];
                    accO[ii] = fma2(pack2(av.x, av.x), sv0, accO[ii]);
                    accO[ii] = fma2(pack2(av.y, av.y), sv1, accO[ii]);
                    accO[ii] = fma2(pack2(av.z, av.z), sv2, accO[ii]);
                    accO[ii] = fma2(pack2(av.w, av.w), sv3, accO[ii]);
                }
            }
        }
        __syncthreads();   // agg reads of B2/B3 done before next head's staging
    }

    // ---- write mean over heads ----
    float* op = outp + bt * 4096;
    #pragma unroll
    for (int ii = 0; ii < 8; ii++) {
        float v0, v1;
        unpack2(accO[ii], v0, v1);
        *(float2*)&op[(w * 8 + ii) * 64 + (l << 1)] = make_float2(0.25f * v0, 0.25f * v1);
    }
}

extern "C" void kernel_launch(void* const* d_in, const int* in_sizes, int n_in,
                              void* d_out, int out_size) {
    const float* feat = (const float*)d_in[0];
    const int*   adj  = (const int*)d_in[1];
    const float* Wsrc = (const float*)d_in[2];
    const float* Wdst = (const float*)d_in[3];
    const float* avec = (const float*)d_in[4];

    const int smem = (256 * LD + 256) * (int)sizeof(float) + 64 * (int)sizeof(unsigned long long);
    cudaFuncSetAttribute((const void*)gat_fused_kernel,
                         cudaFuncAttributeMaxDynamicSharedMemorySize, smem);

    gat_fused_kernel<<<256, 256, smem>>>(feat, adj, Wsrc, Wdst, avec, (float*)d_out);
}

// round 6
// speedup vs baseline: 1.1671x; 1.1026x over previous
#include <cuda_runtime.h>
#include <cuda_bf16.h>
#include <cstdint>

// ---------------------------------------------------------------------------
// GATv2 fused: B=8,T=32,N=64,F=64,U=64,H=4 (BT=256 graphs), one CTA/graph.
// Projections on tensor cores via mma.sync.m16n8k16.bf16 (split-bf16, fp32
// acc, error ~1e-5). Pairwise/softmax/aggregation on CUDA cores (f32x2).
// ---------------------------------------------------------------------------

#define XLD 144      // X row stride bytes (72 bf16)
#define WLD 272      // W row stride bytes (136 bf16)
#define LDs 68       // fp32 tile row stride (floats)
#define OFF_AX 0
#define OFF_BW 18432
#define OFF_SF 53248
#define OFF_DT 70656
#define OFF_SC 88064
#define OFF_AS 105472
#define OFF_A8 105728
#define OFF_PS 105984
#define OFF_QS 106240
#define OFF_ADJ 106496
#define SMEM_TOTAL 107008
#define BLOBSZ 34816  // per-head W blob: [hi;lo][64][136] bf16

__device__ __align__(256) unsigned char g_wblob[4 * BLOBSZ];

__device__ __forceinline__ uint32_t smem_u32(const void* p) {
    uint32_t a;
    asm("{ .reg .u64 t; cvta.to.shared.u64 t, %1; cvt.u32.u64 %0, t; }" : "=r"(a) : "l"(p));
    return a;
}
__device__ __forceinline__ void ldsm4(uint32_t* r, uint32_t a) {
    asm volatile("ldmatrix.sync.aligned.m8n8.x4.shared.b16 {%0,%1,%2,%3}, [%4];"
        : "=r"(r[0]), "=r"(r[1]), "=r"(r[2]), "=r"(r[3]) : "r"(a));
}
__device__ __forceinline__ void ldsm4t(uint32_t* r, uint32_t a) {
    asm volatile("ldmatrix.sync.aligned.m8n8.x4.trans.shared.b16 {%0,%1,%2,%3}, [%4];"
        : "=r"(r[0]), "=r"(r[1]), "=r"(r[2]), "=r"(r[3]) : "r"(a));
}
__device__ __forceinline__ void hmma(float* c, const uint32_t* a, uint32_t b0, uint32_t b1) {
    asm volatile("mma.sync.aligned.m16n8k16.row.col.f32.bf16.bf16.f32 "
        "{%0,%1,%2,%3}, {%4,%5,%6,%7}, {%8,%9}, {%0,%1,%2,%3};"
        : "+f"(c[0]), "+f"(c[1]), "+f"(c[2]), "+f"(c[3])
        : "r"(a[0]), "r"(a[1]), "r"(a[2]), "r"(a[3]), "r"(b0), "r"(b1));
}
__device__ __forceinline__ unsigned long long pack2(float lo, float hi) {
    unsigned long long r; asm("mov.b64 %0, {%1,%2};" : "=l"(r) : "f"(lo), "f"(hi)); return r;
}
__device__ __forceinline__ void unpack2(unsigned long long v, float& lo, float& hi) {
    asm("mov.b64 {%0,%1}, %2;" : "=f"(lo), "=f"(hi) : "l"(v));
}
__device__ __forceinline__ unsigned long long add2(unsigned long long a, unsigned long long b) {
    unsigned long long r; asm("add.rn.f32x2 %0, %1, %2;" : "=l"(r) : "l"(a), "l"(b)); return r;
}
__device__ __forceinline__ unsigned long long fma2(unsigned long long a, unsigned long long b, unsigned long long c) {
    unsigned long long r; asm("fma.rn.f32x2 %0, %1, %2, %3;" : "=l"(r) : "l"(a), "l"(b), "l"(c)); return r;
}
__device__ __forceinline__ unsigned long long relu2(unsigned long long v) {
    float lo, hi; unpack2(v, lo, hi); lo = fmaxf(lo, 0.f); hi = fmaxf(hi, 0.f); return pack2(lo, hi);
}
__device__ __forceinline__ float f4get(const float4& v, int i) {
    switch (i & 3) { case 0: return v.x; case 1: return v.y; case 2: return v.z; default: return v.w; }
}

// W -> bf16 hi/lo split blob, row-major [k][n], n = [Wsrc cols | Wdst cols]
__global__ void prep_w(const float* __restrict__ Ws, const float* __restrict__ Wd) {
    int h = blockIdx.x;
    unsigned char* base = g_wblob + h * BLOBSZ;
    for (int idx = threadIdx.x; idx < 64 * 128; idx += 256) {
        int k = idx >> 7, n = idx & 127;
        float w = (n < 64) ? Ws[h * 4096 + k * 64 + n] : Wd[h * 4096 + k * 64 + (n - 64)];
        __nv_bfloat16 hi = __float2bfloat16(w);
        __nv_bfloat16 lo = __float2bfloat16(w - __bfloat162float(hi));
        int byt = (k * 136 + n) * 2;
        *(unsigned short*)(base + byt)         = __bfloat16_as_ushort(hi);
        *(unsigned short*)(base + 17408 + byt) = __bfloat16_as_ushort(lo);
    }
}

__global__ void __launch_bounds__(256, 2) gat_mma_kernel(
    const float* __restrict__ feat, const int* __restrict__ adj,
    const float* __restrict__ avec, float* __restrict__ outp)
{
    extern __shared__ char smem[];
    const uint32_t sb = smem_u32(smem);
    float* Sf = (float*)(smem + OFF_SF);
    float* Dt = (float*)(smem + OFF_DT);
    float* Sc = (float*)(smem + OFF_SC);
    float* aS = (float*)(smem + OFF_AS);
    float* a8 = (float*)(smem + OFF_A8);
    float* ps = (float*)(smem + OFF_PS);
    float* qs = (float*)(smem + OFF_QS);
    unsigned long long* adjb = (unsigned long long*)(smem + OFF_ADJ);

    const int tid = threadIdx.x, wid = tid >> 5, lid = tid & 31;
    const int bt = blockIdx.x, b = bt >> 5;
    const int ty = tid >> 4, tx = tid & 15;
    const int r0 = ty << 2, c0 = tx << 2;

    // ---- stage X split [Xhi(0-63); Xlo(64-127)] bf16 + adjacency masks ----
    {
        const float4* xp = (const float4*)(feat + bt * 4096);
        for (int idx = tid; idx < 1024; idx += 256) {
            float4 v = xp[idx];
            int i = idx >> 4, f0 = (idx & 15) << 2;
            __nv_bfloat16 hx = __float2bfloat16(v.x), hy = __float2bfloat16(v.y);
            __nv_bfloat16 hz = __float2bfloat16(v.z), hw = __float2bfloat16(v.w);
            uint32_t h01 = ((uint32_t)__bfloat16_as_ushort(hy) << 16) | __bfloat16_as_ushort(hx);
            uint32_t h23 = ((uint32_t)__bfloat16_as_ushort(hw) << 16) | __bfloat16_as_ushort(hz);
            __nv_bfloat16 lx = __float2bfloat16(v.x - __bfloat162float(hx));
            __nv_bfloat16 ly = __float2bfloat16(v.y - __bfloat162float(hy));
            __nv_bfloat16 lz = __float2bfloat16(v.z - __bfloat162float(hz));
            __nv_bfloat16 lw = __float2bfloat16(v.w - __bfloat162float(hw));
            uint32_t l01 = ((uint32_t)__bfloat16_as_ushort(ly) << 16) | __bfloat16_as_ushort(lx);
            uint32_t l23 = ((uint32_t)__bfloat16_as_ushort(lw) << 16) | __bfloat16_as_ushort(lz);
            *(uint2*)(smem + OFF_AX + i * XLD + f0 * 2)         = make_uint2(h01, h23);
            *(uint2*)(smem + OFF_AX + (64 + i) * XLD + f0 * 2)  = make_uint2(l01, l23);
        }
        if (tid < 64) {
            const int* ar = adj + b * 4096 + tid * 64;
            unsigned long long m = 1ull << tid;
            #pragma unroll 8
            for (int j = 0; j < 64; j++) if (ar[j] > 0) m |= (1ull << j);
            adjb[tid] = m;
        }
    }

    unsigned long long accO[8];
    #pragma unroll
    for (int ii = 0; ii < 8; ii++) accO[ii] = 0ull;

    const int mr = lid >> 2, nc = (lid & 3) << 1;
    const int ib = (wid & 3) << 4;           // i-base of this warp's 16 rows
    const bool bot = wid >= 4;               // Xlo rows

    for (int h = 0; h < 4; h++) {
        {   // stage W blob (34816B) + a
            const float4* src = (const float4*)(g_wblob + h * BLOBSZ);
            float4* dst = (float4*)(smem + OFF_BW);
            for (int k = tid; k < BLOBSZ / 16; k += 256) dst[k] = src[k];
            if (tid < 64) {
                float av = avec[h * 64 + tid];
                aS[tid] = av; a8[tid] = 0.8f * av;
            }
        }
        __syncthreads();

        // ---- projection: P[128x128] = [Xhi;Xlo] @ ([Whi] then [Wlo]) ------
        uint32_t afr[4][4];
        {
            uint32_t abase = sb + OFF_AX + (16 * wid + (lid & 15)) * XLD + (lid >> 4) * 16;
            #pragma unroll
            for (int kb = 0; kb < 4; kb++) ldsm4(afr[kb], abase + kb * 32);
        }
        #pragma unroll
        for (int h2 = 0; h2 < 2; h2++) {
            float acc[8][4];
            #pragma unroll
            for (int q = 0; q < 8; q++) { acc[q][0] = acc[q][1] = acc[q][2] = acc[q][3] = 0.f; }
            #pragma unroll
            for (int ks = 0; ks < 8; ks++) {   // 0-3: Whi rows, 4-7: Wlo rows
                uint32_t wb = sb + OFF_BW + (ks * 16 + (lid & 15)) * WLD
                            + h2 * 128 + (lid >> 4) * 16;
                #pragma unroll
                for (int np = 0; np < 4; np++) {
                    uint32_t bf[4];
                    ldsm4t(bf, wb + np * 32);
                    hmma(acc[2 * np],     afr[ks & 3], bf[0], bf[1]);
                    hmma(acc[2 * np + 1], afr[ks & 3], bf[2], bf[3]);
                }
            }
            // epilogue: bot writes, sync, top adds. h2=0 -> Sf (S), h2=1 -> Dt (D^T)
            if (bot) {
                #pragma unroll
                for (int nt = 0; nt < 8; nt++) {
                    int n = nt * 8 + nc;
                    if (h2 == 0) {
                        *(float2*)&Sf[(ib + mr) * LDs + n]     = make_float2(acc[nt][0], acc[nt][1]);
                        *(float2*)&Sf[(ib + mr + 8) * LDs + n] = make_float2(acc[nt][2], acc[nt][3]);
                    } else {
                        Dt[n * LDs + ib + mr]           = acc[nt][0];
                        Dt[(n + 1) * LDs + ib + mr]     = acc[nt][1];
                        Dt[n * LDs + ib + mr + 8]       = acc[nt][2];
                        Dt[(n + 1) * LDs + ib + mr + 8] = acc[nt][3];
                    }
                }
            }
            __syncthreads();
            if (!bot) {
                #pragma unroll
                for (int nt = 0; nt < 8; nt++) {
                    int n = nt * 8 + nc;
                    if (h2 == 0) {
                        float2 t0 = *(const float2*)&Sf[(ib + mr) * LDs + n];
                        float2 t1 = *(const float2*)&Sf[(ib + mr + 8) * LDs + n];
                        t0.x += acc[nt][0]; t0.y += acc[nt][1];
                        t1.x += acc[nt][2]; t1.y += acc[nt][3];
                        *(float2*)&Sf[(ib + mr) * LDs + n]     = t0;
                        *(float2*)&Sf[(ib + mr + 8) * LDs + n] = t1;
                    } else {
                        Dt[n * LDs + ib + mr]           += acc[nt][0];
                        Dt[(n + 1) * LDs + ib + mr]     += acc[nt][1];
                        Dt[n * LDs + ib + mr + 8]       += acc[nt][2];
                        Dt[(n + 1) * LDs + ib + mr + 8] += acc[nt][3];
                    }
                }
            }
            __syncthreads();
        }

        // ---- p_i = S.a, q_j = D.a ----
        if (tid < 64) {
            float accp = 0.f, accq = 0.f;
            #pragma unroll 8
            for (int u = 0; u < 64; u++) {
                accp += aS[u] * Sf[tid * LDs + u];
                accq += aS[u] * Dt[u * LDs + tid];
            }
            ps[tid] = accp; qs[tid] = accq;
        }
        __syncthreads();

        // ---- pairwise: 0.2*(p_i+q_j) + sum_u 0.8*a_u*relu(s_iu+d_ju) ----
        {
            unsigned long long acc0[4], acc1[4];
            #pragma unroll
            for (int ii = 0; ii < 4; ii++) { acc0[ii] = 0ull; acc1[ii] = 0ull; }
            #pragma unroll 2
            for (int u4 = 0; u4 < 64; u4 += 4) {
                float4 a84 = *(const float4*)&a8[u4];
                float4 s0 = *(const float4*)&Sf[(r0 + 0) * LDs + u4];
                float4 s1 = *(const float4*)&Sf[(r0 + 1) * LDs + u4];
                float4 s2 = *(const float4*)&Sf[(r0 + 2) * LDs + u4];
                float4 s3 = *(const float4*)&Sf[(r0 + 3) * LDs + u4];
                #pragma unroll
                for (int uu = 0; uu < 4; uu++) {
                    ulonglong2 d2 = *(const ulonglong2*)&Dt[(u4 + uu) * LDs + c0];
                    float a8u = f4get(a84, uu);
                    unsigned long long a2 = pack2(a8u, a8u);
#define PR(K, SR) { float s_ = f4get(SR, uu); unsigned long long s2_ = pack2(s_, s_); \
                    acc0[K] = fma2(a2, relu2(add2(s2_, d2.x)), acc0[K]);              \
                    acc1[K] = fma2(a2, relu2(add2(s2_, d2.y)), acc1[K]); }
                    PR(0, s0) PR(1, s1) PR(2, s2) PR(3, s3)
#undef PR
                }
            }
            float q0 = qs[c0], q1 = qs[c0 + 1], q2 = qs[c0 + 2], q3 = qs[c0 + 3];
            #pragma unroll
            for (int ii = 0; ii < 4; ii++) {
                float pi = ps[r0 + ii], v0, v1, v2, v3;
                unpack2(acc0[ii], v0, v1); unpack2(acc1[ii], v2, v3);
                float4 sc;
                sc.x = 0.2f * (pi + q0) + v0; sc.y = 0.2f * (pi + q1) + v1;
                sc.z = 0.2f * (pi + q2) + v2; sc.w = 0.2f * (pi + q3) + v3;
                *(float4*)&Sc[(r0 + ii) * LDs + c0] = sc;
            }
        }
        __syncthreads();

        // ---- masked softmax (4 threads/row) ----
        {
            int row = tid >> 2, qd = tid & 3;
            float* srow = Sc + row * LDs + (qd << 4);
            unsigned mb = (unsigned)(adjb[row] >> (qd << 4)) & 0xFFFFu;
            float vals[16], mx = -3.0e38f;
            #pragma unroll
            for (int c = 0; c < 16; c++) {
                float v = ((mb >> c) & 1u) ? srow[c] : -1e9f;
                vals[c] = v; mx = fmaxf(mx, v);
            }
            mx = fmaxf(mx, __shfl_xor_sync(~0u, mx, 1));
            mx = fmaxf(mx, __shfl_xor_sync(~0u, mx, 2));
            float ssum = 0.f;
            #pragma unroll
            for (int c = 0; c < 16; c++) {
                float e = exp2f((vals[c] - mx) * 1.4426950408889634f);
                vals[c] = e; ssum += e;
            }
            ssum += __shfl_xor_sync(~0u, ssum, 1);
            ssum += __shfl_xor_sync(~0u, ssum, 2);
            float inv = 1.0f / ssum;
            #pragma unroll
            for (int c = 0; c < 16; c++) srow[c] = vals[c] * inv;
        }
        __syncthreads();

        // ---- aggregation: accO += attn @ S (packed f32x2) ----
        {
            const int l2 = lid << 1;
            #pragma unroll 2
            for (int j4 = 0; j4 < 64; j4 += 4) {
                unsigned long long sv0 = *(const unsigned long long*)&Sf[(j4 + 0) * LDs + l2];
                unsigned long long sv1 = *(const unsigned long long*)&Sf[(j4 + 1) * LDs + l2];
                unsigned long long sv2 = *(const unsigned long long*)&Sf[(j4 + 2) * LDs + l2];
                unsigned long long sv3 = *(const unsigned long long*)&Sf[(j4 + 3) * LDs + l2];
                #pragma unroll
                for (int ii = 0; ii < 8; ii++) {
                    float4 av = *(const float4*)&Sc[(wid * 8 + ii) * LDs + j4];
                    accO[ii] = fma2(pack2(av.x, av.x), sv0, accO[ii]);
                    accO[ii] = fma2(pack2(av.y, av.y), sv1, accO[ii]);
                    accO[ii] = fma2(pack2(av.z, av.z), sv2, accO[ii]);
                    accO[ii] = fma2(pack2(av.w, av.w), sv3, accO[ii]);
                }
            }
        }
        __syncthreads();
    }

    // ---- write mean over heads ----
    float* op = outp + bt * 4096;
    #pragma unroll
    for (int ii = 0; ii < 8; ii++) {
        float v0, v1;
        unpack2(accO[ii], v0, v1);
        *(float2*)&op[(wid * 8 + ii) * 64 + (lid << 1)] = make_float2(0.25f * v0, 0.25f * v1);
    }
}

extern "C" void kernel_launch(void* const* d_in, const int* in_sizes, int n_in,
                              void* d_out, int out_size) {
    const float* feat = (const float*)d_in[0];
    const int*   adj  = (const int*)d_in[1];
    const float* Wsrc = (const float*)d_in[2];
    const float* Wdst = (const float*)d_in[3];
    const float* avec = (const float*)d_in[4];

    cudaFuncSetAttribute((const void*)gat_mma_kernel,
                         cudaFuncAttributeMaxDynamicSharedMemorySize, SMEM_TOTAL);
    prep_w<<<4, 256>>>(Wsrc, Wdst);
    gat_mma_kernel<<<256, 256, SMEM_TOTAL>>>(feat, adj, avec, (float*)d_out);
}

// round 9
// speedup vs baseline: 1.3793x; 1.1818x over previous
#include <cuda_runtime.h>
#include <cuda_bf16.h>
#include <cstdint>

// GATv2 fused: B=8,T=32,N=64,F=64,U=64,H=4 (BT=256), one CTA/graph.
// Projection AND aggregation on mma.sync.m16n8k16.bf16 (3-term split, fp32 acc).
// Pairwise scores + softmax on CUDA cores (packed f32x2).

#define XLD 144      // X bf16 row stride bytes
#define WLD 272      // W / ATT / SBF bf16 row stride bytes (128 data cols + pad)
#define LDs 68       // fp32 tile row stride (floats)
#define OFF_AX 0
#define OFF_BW 18432
#define OFF_ATT 18432            // overlay: attn bf16 split (after proj)
#define OFF_SBF (18432 + 17408)  // overlay: S bf16 split
#define OFF_SF 53248
#define OFF_DT 70656
#define OFF_SC 88064
#define OFF_AS 105472
#define OFF_A8 105728
#define OFF_PS 105984
#define OFF_QS 106240
#define OFF_ADJ 106496
#define SMEM_TOTAL 107008
#define BLOBSZ 34816

__device__ __align__(256) unsigned char g_wblob[4 * BLOBSZ];

__device__ __forceinline__ uint32_t smem_u32(const void* p) {
    uint32_t a;
    asm("{ .reg .u64 t; cvta.to.shared.u64 t, %1; cvt.u32.u64 %0, t; }" : "=r"(a) : "l"(p));
    return a;
}
__device__ __forceinline__ void ldsm4(uint32_t* r, uint32_t a) {
    asm volatile("ldmatrix.sync.aligned.m8n8.x4.shared.b16 {%0,%1,%2,%3}, [%4];"
        : "=r"(r[0]), "=r"(r[1]), "=r"(r[2]), "=r"(r[3]) : "r"(a));
}
__device__ __forceinline__ void ldsm4t(uint32_t* r, uint32_t a) {
    asm volatile("ldmatrix.sync.aligned.m8n8.x4.trans.shared.b16 {%0,%1,%2,%3}, [%4];"
        : "=r"(r[0]), "=r"(r[1]), "=r"(r[2]), "=r"(r[3]) : "r"(a));
}
__device__ __forceinline__ void hmma(float* c, const uint32_t* a, uint32_t b0, uint32_t b1) {
    asm volatile("mma.sync.aligned.m16n8k16.row.col.f32.bf16.bf16.f32 "
        "{%0,%1,%2,%3}, {%4,%5,%6,%7}, {%8,%9}, {%0,%1,%2,%3};"
        : "+f"(c[0]), "+f"(c[1]), "+f"(c[2]), "+f"(c[3])
        : "r"(a[0]), "r"(a[1]), "r"(a[2]), "r"(a[3]), "r"(b0), "r"(b1));
}
__device__ __forceinline__ unsigned long long pack2(float lo, float hi) {
    unsigned long long r; asm("mov.b64 %0, {%1,%2};" : "=l"(r) : "f"(lo), "f"(hi)); return r;
}
__device__ __forceinline__ void unpack2(unsigned long long v, float& lo, float& hi) {
    asm("mov.b64 {%0,%1}, %2;" : "=f"(lo), "=f"(hi) : "l"(v));
}
__device__ __forceinline__ unsigned long long add2(unsigned long long a, unsigned long long b) {
    unsigned long long r; asm("add.rn.f32x2 %0, %1, %2;" : "=l"(r) : "l"(a), "l"(b)); return r;
}
__device__ __forceinline__ unsigned long long fma2(unsigned long long a, unsigned long long b, unsigned long long c) {
    unsigned long long r; asm("fma.rn.f32x2 %0, %1, %2, %3;" : "=l"(r) : "l"(a), "l"(b), "l"(c)); return r;
}
__device__ __forceinline__ unsigned long long relu2(unsigned long long v) {
    float lo, hi; unpack2(v, lo, hi); lo = fmaxf(lo, 0.f); hi = fmaxf(hi, 0.f); return pack2(lo, hi);
}
__device__ __forceinline__ float f4get(const float4& v, int i) {
    switch (i & 3) { case 0: return v.x; case 1: return v.y; case 2: return v.z; default: return v.w; }
}
__device__ __forceinline__ void split2(float v0, float v1, uint32_t& hw, uint32_t& lw) {
    __nv_bfloat16 h0 = __float2bfloat16(v0), h1 = __float2bfloat16(v1);
    hw = ((uint32_t)__bfloat16_as_ushort(h1) << 16) | __bfloat16_as_ushort(h0);
    __nv_bfloat16 l0 = __float2bfloat16(v0 - __bfloat162float(h0));
    __nv_bfloat16 l1 = __float2bfloat16(v1 - __bfloat162float(h1));
    lw = ((uint32_t)__bfloat16_as_ushort(l1) << 16) | __bfloat16_as_ushort(l0);
}

__global__ void prep_w(const float* __restrict__ Ws, const float* __restrict__ Wd) {
    int h = blockIdx.x;
    unsigned char* base = g_wblob + h * BLOBSZ;
    for (int idx = threadIdx.x; idx < 64 * 128; idx += 256) {
        int k = idx >> 7, n = idx & 127;
        float w = (n < 64) ? Ws[h * 4096 + k * 64 + n] : Wd[h * 4096 + k * 64 + (n - 64)];
        __nv_bfloat16 hi = __float2bfloat16(w);
        __nv_bfloat16 lo = __float2bfloat16(w - __bfloat162float(hi));
        int byt = (k * 136 + n) * 2;
        *(unsigned short*)(base + byt)         = __bfloat16_as_ushort(hi);
        *(unsigned short*)(base + 17408 + byt) = __bfloat16_as_ushort(lo);
    }
}

__global__ void __launch_bounds__(256, 2) gat_mma_kernel(
    const float* __restrict__ feat, const int* __restrict__ adj,
    const float* __restrict__ avec, float* __restrict__ outp)
{
    extern __shared__ char smem[];
    const uint32_t sb = smem_u32(smem);   // shared-space addr: ONLY for ldmatrix/mma asm
    float* Sf = (float*)(smem + OFF_SF);
    float* Dt = (float*)(smem + OFF_DT);
    float* Sc = (float*)(smem + OFF_SC);
    float* aS = (float*)(smem + OFF_AS);
    float* a8 = (float*)(smem + OFF_A8);
    float* ps = (float*)(smem + OFF_PS);
    float* qs = (float*)(smem + OFF_QS);
    unsigned long long* adjb = (unsigned long long*)(smem + OFF_ADJ);

    const int tid = threadIdx.x, wid = tid >> 5, lid = tid & 31;
    const int bt = blockIdx.x, b = bt >> 5;
    const int ty = tid >> 4, tx = tid & 15;
    const int r0 = ty << 2, c0 = tx << 2;
    const int mr = lid >> 2, nc = (lid & 3) << 1;
    const int ib = (wid & 3) << 4;   // 16-row block for proj AND agg
    const int nh = wid >> 2;         // proj: 0->S half, 1->D half; agg: u-half

    // ---- stage X split [Xhi rows 0-63; Xlo rows 64-127] + adjacency ----
    {
        const float4* xp = (const float4*)(feat + bt * 4096);
        for (int idx = tid; idx < 1024; idx += 256) {
            float4 v = xp[idx];
            int i = idx >> 4, f0 = (idx & 15) << 2;
            uint32_t h01, l01, h23, l23;
            split2(v.x, v.y, h01, l01);
            split2(v.z, v.w, h23, l23);
            *(uint2*)(smem + OFF_AX + i * XLD + f0 * 2)        = make_uint2(h01, h23);
            *(uint2*)(smem + OFF_AX + (64 + i) * XLD + f0 * 2) = make_uint2(l01, l23);
        }
        if (tid < 64) {
            const int* ar = adj + b * 4096 + tid * 64;
            unsigned long long m = 1ull << tid;
            #pragma unroll 8
            for (int j = 0; j < 64; j++) if (ar[j] > 0) m |= (1ull << j);
            adjb[tid] = m;
        }
    }

    float cacc[4][4];   // agg accumulators: 16x32 tile, persist across heads
    #pragma unroll
    for (int t = 0; t < 4; t++) { cacc[t][0] = cacc[t][1] = cacc[t][2] = cacc[t][3] = 0.f; }

    for (int h = 0; h < 4; h++) {
        {   // stage W blob + a
            const float4* src = (const float4*)(g_wblob + h * BLOBSZ);
            float4* dst = (float4*)(smem + OFF_BW);
            for (int k = tid; k < BLOBSZ / 16; k += 256) dst[k] = src[k];
            if (tid < 64) {
                float av = avec[h * 64 + tid];
                aS[tid] = av; a8[tid] = 0.8f * av;
            }
        }
        __syncthreads();

        // ---- projection (3-pass): warp = (m-block ib, half nh). K=64 each pass.
        {
            uint32_t ahi[4][4], alo[4][4];
            uint32_t abase = sb + OFF_AX + (ib + (lid & 15)) * XLD + ((lid >> 4) << 4);
            #pragma unroll
            for (int kc = 0; kc < 4; kc++) {
                ldsm4(ahi[kc], abase + kc * 32);
                ldsm4(alo[kc], abase + 64 * XLD + kc * 32);
            }
            float pacc[8][4];
            #pragma unroll
            for (int t = 0; t < 8; t++) { pacc[t][0] = pacc[t][1] = pacc[t][2] = pacc[t][3] = 0.f; }
            #pragma unroll
            for (int pass = 0; pass < 3; pass++) {
                const int wofs = (pass == 2) ? 17408 : 0;
                #pragma unroll
                for (int kc = 0; kc < 4; kc++) {
                    const uint32_t* af = (pass == 1) ? alo[kc] : ahi[kc];
                    uint32_t wb = sb + OFF_BW + wofs + ((kc << 4) + (lid & 15)) * WLD
                                + nh * 128 + ((lid >> 4) << 4);
                    #pragma unroll
                    for (int np = 0; np < 4; np++) {
                        uint32_t bf[4];
                        ldsm4t(bf, wb + np * 32);
                        hmma(pacc[2 * np],     af, bf[0], bf[1]);
                        hmma(pacc[2 * np + 1], af, bf[2], bf[3]);
                    }
                }
            }
            if (nh == 0) {      // S rows, row-major
                #pragma unroll
                for (int nt = 0; nt < 8; nt++) {
                    int u = (nt << 3) + nc;
                    *(float2*)&Sf[(ib + mr) * LDs + u]     = make_float2(pacc[nt][0], pacc[nt][1]);
                    *(float2*)&Sf[(ib + mr + 8) * LDs + u] = make_float2(pacc[nt][2], pacc[nt][3]);
                }
            } else {            // D -> transposed Dt[u][j]
                #pragma unroll
                for (int nt = 0; nt < 8; nt++) {
                    int u = (nt << 3) + nc;
                    Dt[u * LDs + ib + mr]           = pacc[nt][0];
                    Dt[(u + 1) * LDs + ib + mr]     = pacc[nt][1];
                    Dt[u * LDs + ib + mr + 8]       = pacc[nt][2];
                    Dt[(u + 1) * LDs + ib + mr + 8] = pacc[nt][3];
                }
            }
        }
        __syncthreads();

        // ---- p/q (all threads) + emit S bf16 split (SBF) ----
        {
            int j = tid >> 2, qd = tid & 3, ug = qd << 4;
            float pv = 0.f, qv = 0.f;
            unsigned char* sb_row = (unsigned char*)smem + OFF_SBF + j * WLD;  // generic ptr
            #pragma unroll
            for (int c4 = 0; c4 < 16; c4 += 4) {
                float4 sv = *(const float4*)&Sf[j * LDs + ug + c4];
                float4 av = *(const float4*)&aS[ug + c4];
                pv += av.x * sv.x + av.y * sv.y + av.z * sv.z + av.w * sv.w;
                uint32_t hw0, lw0, hw1, lw1;
                split2(sv.x, sv.y, hw0, lw0);
                split2(sv.z, sv.w, hw1, lw1);
                *(uint32_t*)(sb_row + (ug + c4) * 2)           = hw0;
                *(uint32_t*)(sb_row + (ug + c4 + 2) * 2)       = hw1;
                *(uint32_t*)(sb_row + 128 + (ug + c4) * 2)     = lw0;
                *(uint32_t*)(sb_row + 128 + (ug + c4 + 2) * 2) = lw1;
            }
            #pragma unroll
            for (int c = 0; c < 16; c++)
                qv += aS[ug + c] * Dt[(ug + c) * LDs + j];
            pv += __shfl_xor_sync(~0u, pv, 1); pv += __shfl_xor_sync(~0u, pv, 2);
            qv += __shfl_xor_sync(~0u, qv, 1); qv += __shfl_xor_sync(~0u, qv, 2);
            if (qd == 0) { ps[j] = pv; qs[j] = qv; }
        }
        __syncthreads();

        // ---- pairwise: 0.2*(p_i+q_j) + sum_u 0.8*a_u*relu(s_iu+d_ju) ----
        {
            unsigned long long acc0[4], acc1[4];
            #pragma unroll
            for (int ii = 0; ii < 4; ii++) { acc0[ii] = 0ull; acc1[ii] = 0ull; }
            #pragma unroll 2
            for (int u4 = 0; u4 < 64; u4 += 4) {
                float4 a84 = *(const float4*)&a8[u4];
                float4 s0 = *(const float4*)&Sf[(r0 + 0) * LDs + u4];
                float4 s1 = *(const float4*)&Sf[(r0 + 1) * LDs + u4];
                float4 s2 = *(const float4*)&Sf[(r0 + 2) * LDs + u4];
                float4 s3 = *(const float4*)&Sf[(r0 + 3) * LDs + u4];
                #pragma unroll
                for (int uu = 0; uu < 4; uu++) {
                    ulonglong2 d2 = *(const ulonglong2*)&Dt[(u4 + uu) * LDs + c0];
                    float a8u = f4get(a84, uu);
                    unsigned long long a2 = pack2(a8u, a8u);
#define PR(K, SR) { float s_ = f4get(SR, uu); unsigned long long s2_ = pack2(s_, s_); \
                    acc0[K] = fma2(a2, relu2(add2(s2_, d2.x)), acc0[K]);              \
                    acc1[K] = fma2(a2, relu2(add2(s2_, d2.y)), acc1[K]); }
                    PR(0, s0) PR(1, s1) PR(2, s2) PR(3, s3)
#undef PR
                }
            }
            float q0 = qs[c0], q1 = qs[c0 + 1], q2 = qs[c0 + 2], q3 = qs[c0 + 3];
            #pragma unroll
            for (int ii = 0; ii < 4; ii++) {
                float pi = ps[r0 + ii], v0, v1, v2, v3;
                unpack2(acc0[ii], v0, v1); unpack2(acc1[ii], v2, v3);
                float4 sc;
                sc.x = 0.2f * (pi + q0) + v0; sc.y = 0.2f * (pi + q1) + v1;
                sc.z = 0.2f * (pi + q2) + v2; sc.w = 0.2f * (pi + q3) + v3;
                *(float4*)&Sc[(r0 + ii) * LDs + c0] = sc;
            }
        }
        __syncthreads();

        // ---- masked softmax -> emit attn bf16 split (ATT) ----
        {
            int row = tid >> 2, qd = tid & 3;
            const float* srow = Sc + row * LDs + (qd << 4);
            unsigned mb = (unsigned)(adjb[row] >> (qd << 4)) & 0xFFFFu;
            float vals[16], mx = -3.0e38f;
            #pragma unroll
            for (int c = 0; c < 16; c++) {
                float v = ((mb >> c) & 1u) ? srow[c] : -1e9f;
                vals[c] = v; mx = fmaxf(mx, v);
            }
            mx = fmaxf(mx, __shfl_xor_sync(~0u, mx, 1));
            mx = fmaxf(mx, __shfl_xor_sync(~0u, mx, 2));
            float ssum = 0.f;
            #pragma unroll
            for (int c = 0; c < 16; c++) {
                float e = exp2f((vals[c] - mx) * 1.4426950408889634f);
                vals[c] = e; ssum += e;
            }
            ssum += __shfl_xor_sync(~0u, ssum, 1);
            ssum += __shfl_xor_sync(~0u, ssum, 2);
            float inv = 1.0f / ssum;
            unsigned char* at_row = (unsigned char*)smem + OFF_ATT + row * WLD + (qd << 5);
            #pragma unroll
            for (int c = 0; c < 16; c += 2) {
                uint32_t hw, lw;
                split2(vals[c] * inv, vals[c + 1] * inv, hw, lw);
                *(uint32_t*)(at_row + c * 2)       = hw;
                *(uint32_t*)(at_row + 128 + c * 2) = lw;
            }
        }
        __syncthreads();

        // ---- aggregation on HMMA: cacc += attn @ S (3-pass split) ----
        {
            uint32_t athi[4][4], atlo[4][4];
            uint32_t tb = sb + OFF_ATT + (ib + (lid & 15)) * WLD + ((lid >> 4) << 4);
            #pragma unroll
            for (int kc = 0; kc < 4; kc++) {
                ldsm4(athi[kc], tb + kc * 32);
                ldsm4(atlo[kc], tb + 128 + kc * 32);
            }
            #pragma unroll
            for (int pass = 0; pass < 3; pass++) {
                const int sofs = (pass == 2) ? 128 : 0;
                #pragma unroll
                for (int kc = 0; kc < 4; kc++) {
                    const uint32_t* af = (pass == 1) ? atlo[kc] : athi[kc];
                    uint32_t sbB = sb + OFF_SBF + ((kc << 4) + (lid & 15)) * WLD
                                 + sofs + nh * 64 + ((lid >> 4) << 4);
                    #pragma unroll
                    for (int np = 0; np < 2; np++) {
                        uint32_t bf[4];
                        ldsm4t(bf, sbB + np * 32);
                        hmma(cacc[2 * np],     af, bf[0], bf[1]);
                        hmma(cacc[2 * np + 1], af, bf[2], bf[3]);
                    }
                }
            }
        }
        __syncthreads();   // ATT/SBF dead before next head's W staging
    }

    // ---- write mean over heads: warp covers rows ib..ib+15, u-half nh ----
    float* op = outp + bt * 4096;
    #pragma unroll
    for (int nt = 0; nt < 4; nt++) {
        int u = (nh << 5) + (nt << 3) + nc;
        *(float2*)&op[(ib + mr) * 64 + u]     = make_float2(0.25f * cacc[nt][0], 0.25f * cacc[nt][1]);
        *(float2*)&op[(ib + mr + 8) * 64 + u] = make_float2(0.25f * cacc[nt][2], 0.25f * cacc[nt][3]);
    }
}

extern "C" void kernel_launch(void* const* d_in, const int* in_sizes, int n_in,
                              void* d_out, int out_size) {
    const float* feat = (const float*)d_in[0];
    const int*   adj  = (const int*)d_in[1];
    const float* Wsrc = (const float*)d_in[2];
    const float* Wdst = (const float*)d_in[3];
    const float* avec = (const float*)d_in[4];

    cudaFuncSetAttribute((const void*)gat_mma_kernel,
                         cudaFuncAttributeMaxDynamicSharedMemorySize, SMEM_TOTAL);
    prep_w<<<4, 256>>>(Wsrc, Wdst);
    gat_mma_kernel<<<256, 256, SMEM_TOTAL>>>(feat, adj, avec, (float*)d_out);
}